// round 5
// baseline (speedup 1.0000x reference)
#include <cuda_runtime.h>

#define BB   512
#define CC   512
#define KK   512
#define EE   16
#define NT   256

#define Z_OFF   0
#define ZE_OFF  ((size_t)BB * CC * EE)            // 4,194,304 floats
#define OH_OFF  ((size_t)2 * BB * CC * EE)        // 8,388,608 floats

#define NZB  80                                    // zero-streamer blocks
#define GRID (CC + NZB)                            // 592 = 148 SMs * 4

typedef unsigned long long u64;

__device__ int g_idx[CC * BB];                     // argmin scratch, [c][b]

__device__ __forceinline__ u64 pack2(float a, float b) {
    u64 r;
    asm("mov.b64 %0, {%1, %2};" : "=l"(r) : "f"(a), "f"(b));
    return r;
}
__device__ __forceinline__ void fma2(u64 &d, u64 a, u64 b) {
    asm("fma.rn.f32x2 %0, %1, %2, %0;" : "+l"(d) : "l"(a), "l"(b));
}
__device__ __forceinline__ void unpack2(float &lo, float &hi, u64 v) {
    asm("mov.b64 {%0, %1}, %2;" : "=f"(lo), "=f"(hi) : "l"(v));
}

// Dynamic smem (34,816 B): sdict float[KK*EE] (32 KB), snrm float[KK] (2 KB)
__global__ void __launch_bounds__(NT, 4) vq_kernel(const float* __restrict__ mu,
                                                   const float* __restrict__ dict,
                                                   float* __restrict__ out)
{
    const int t = threadIdx.x;

    // ================= zero-streamer blocks =================
    if (blockIdx.x >= CC) {
        const int z = blockIdx.x - CC;                        // 0..NZB-1
        float4* p = (float4*)(out + OH_OFF);
        const int total = BB * CC * KK / 4;                   // 33,554,432 float4
        const int stride = NZB * NT;                          // 20,480
        const float4 z4 = make_float4(0.f, 0.f, 0.f, 0.f);
        int i = z * NT + t;
#pragma unroll 4
        for (; i < total; i += stride) p[i] = z4;
        return;
    }

    // ================= compute blocks (one code c each) =================
    extern __shared__ float smem_f[];
    float* sdict = smem_f;
    float* snrm  = smem_f + KK * EE;
    const int c = blockIdx.x;

    // ---- this thread's 2 batch rows (t, t+256), packed pairwise over e ----
    u64 muA[EE / 2], muB[EE / 2];
    {
        const float* m0 = mu + (size_t)t         * (CC * EE) + c * EE;
        const float* m1 = mu + (size_t)(t + 256) * (CC * EE) + c * EE;
#pragma unroll
        for (int e = 0; e < EE; e += 4) {
            float4 a = *(const float4*)(m0 + e);
            float4 b = *(const float4*)(m1 + e);
            muA[e / 2] = pack2(a.x, a.y);  muA[e / 2 + 1] = pack2(a.z, a.w);
            muB[e / 2] = pack2(b.x, b.y);  muB[e / 2 + 1] = pack2(b.z, b.w);
        }
    }

    // ---- dict[c] -> smem ----
    {
        const float4* g = (const float4*)(dict + (size_t)c * KK * EE);
        float4* sd4 = (float4*)sdict;
#pragma unroll 4
        for (int i = t; i < KK * EE / 4; i += NT) sd4[i] = g[i];
    }
    __syncthreads();

    // ---- -0.5 * ||d_k||^2 ----
#pragma unroll
    for (int k = t; k < KK; k += NT) {
        const float4* dv = (const float4*)(sdict + k * EE);
        float s = 0.f;
#pragma unroll
        for (int j = 0; j < 4; j++) {
            float4 v = dv[j];
            s = fmaf(v.x, v.x, s); s = fmaf(v.y, v.y, s);
            s = fmaf(v.z, v.z, s); s = fmaf(v.w, v.w, s);
        }
        snrm[k] = -0.5f * s;
    }
    __syncthreads();

    // ---- main argmax loop (k-pairs), pure LDS + FMA2 ----
    float best0 = -3.4e38f, best1 = -3.4e38f;
    int i0 = 0, i1 = 0;
    const ulonglong2* dq = (const ulonglong2*)sdict;       // 8 per k-pair

    for (int it = 0; it < KK / 2; ++it) {
        const int k = 2 * it;
        const float n0 = snrm[k], n1 = snrm[k + 1];
        float lo, hi, s;

        {   // k
            ulonglong2 q0 = dq[0], q1 = dq[1], q2 = dq[2], q3 = dq[3];
            u64 a0 = pack2(n0, 0.f), a1 = a0;
            fma2(a0, muA[0], q0.x); fma2(a1, muB[0], q0.x);
            fma2(a0, muA[1], q0.y); fma2(a1, muB[1], q0.y);
            fma2(a0, muA[2], q1.x); fma2(a1, muB[2], q1.x);
            fma2(a0, muA[3], q1.y); fma2(a1, muB[3], q1.y);
            fma2(a0, muA[4], q2.x); fma2(a1, muB[4], q2.x);
            fma2(a0, muA[5], q2.y); fma2(a1, muB[5], q2.y);
            fma2(a0, muA[6], q3.x); fma2(a1, muB[6], q3.x);
            fma2(a0, muA[7], q3.y); fma2(a1, muB[7], q3.y);
            unpack2(lo, hi, a0); s = lo + hi;
            if (s > best0) { best0 = s; i0 = k; }
            unpack2(lo, hi, a1); s = lo + hi;
            if (s > best1) { best1 = s; i1 = k; }
        }
        {   // k+1
            ulonglong2 q4 = dq[4], q5 = dq[5], q6 = dq[6], q7 = dq[7];
            u64 a2 = pack2(n1, 0.f), a3 = a2;
            fma2(a2, muA[0], q4.x); fma2(a3, muB[0], q4.x);
            fma2(a2, muA[1], q4.y); fma2(a3, muB[1], q4.y);
            fma2(a2, muA[2], q5.x); fma2(a3, muB[2], q5.x);
            fma2(a2, muA[3], q5.y); fma2(a3, muB[3], q5.y);
            fma2(a2, muA[4], q6.x); fma2(a3, muB[4], q6.x);
            fma2(a2, muA[5], q6.y); fma2(a3, muB[5], q6.y);
            fma2(a2, muA[6], q7.x); fma2(a3, muB[6], q7.x);
            fma2(a2, muA[7], q7.y); fma2(a3, muB[7], q7.y);
            unpack2(lo, hi, a2); s = lo + hi;
            if (s > best0) { best0 = s; i0 = k + 1; }
            unpack2(lo, hi, a3); s = lo + hi;
            if (s > best1) { best1 = s; i1 = k + 1; }
        }
        dq += 8;
    }

    // ---- write z / z_embed; record indices for the ones kernel ----
    {
        const float* v = sdict + i0 * EE;
        size_t off = (size_t)t * (CC * EE) + c * EE;
#pragma unroll
        for (int e = 0; e < EE; e += 4) {
            float4 vv = *(const float4*)(v + e);
            float mx, my, mz, mw;
            unpack2(mx, my, muA[e / 2]);
            unpack2(mz, mw, muA[e / 2 + 1]);
            float4 zz;
            zz.x = mx + (vv.x - mx); zz.y = my + (vv.y - my);
            zz.z = mz + (vv.z - mz); zz.w = mw + (vv.w - mw);
            *(float4*)(out + Z_OFF  + off + e) = zz;
            *(float4*)(out + ZE_OFF + off + e) = vv;
        }
    }
    {
        const float* v = sdict + i1 * EE;
        size_t off = (size_t)(t + 256) * (CC * EE) + c * EE;
#pragma unroll
        for (int e = 0; e < EE; e += 4) {
            float4 vv = *(const float4*)(v + e);
            float mx, my, mz, mw;
            unpack2(mx, my, muB[e / 2]);
            unpack2(mz, mw, muB[e / 2 + 1]);
            float4 zz;
            zz.x = mx + (vv.x - mx); zz.y = my + (vv.y - my);
            zz.z = mz + (vv.z - mz); zz.w = mw + (vv.w - mw);
            *(float4*)(out + Z_OFF  + off + e) = zz;
            *(float4*)(out + ZE_OFF + off + e) = vv;
        }
    }
    g_idx[c * BB + t]       = i0;
    g_idx[c * BB + t + 256] = i1;
}

// Scatter the ones (runs after all zeros are down; stream-ordered).
__global__ void __launch_bounds__(NT) ones_kernel(float* __restrict__ out)
{
    const int tid = blockIdx.x * NT + threadIdx.x;   // 0 .. CC*BB-1
    const int c = tid >> 9;
    const int b = tid & (BB - 1);
    const int k = g_idx[tid];
    out[OH_OFF + (size_t)b * (CC * KK) + (size_t)c * KK + k] = 1.0f;
}

extern "C" void kernel_launch(void* const* d_in, const int* in_sizes, int n_in,
                              void* d_out, int out_size)
{
    (void)in_sizes; (void)n_in; (void)out_size;
    const float* mu   = (const float*)d_in[0];
    const float* dict = (const float*)d_in[1];
    float* out = (float*)d_out;

    const int smem = (KK * EE + KK) * 4;   // 34,816 bytes
    cudaFuncSetAttribute(vq_kernel, cudaFuncAttributeMaxDynamicSharedMemorySize, smem);
    vq_kernel<<<GRID, NT, smem>>>(mu, dict, out);
    ones_kernel<<<CC * BB / NT, NT>>>(out);
}

// round 6
// speedup vs baseline: 1.2572x; 1.2572x over previous
#include <cuda_runtime.h>

#define BB   512
#define CC   512
#define KK   512
#define EE   16
#define NT   256

#define Z_OFF   0
#define ZE_OFF  ((size_t)BB * CC * EE)            // 4,194,304 floats
#define OH_OFF  ((size_t)2 * BB * CC * EE)        // 8,388,608 floats

typedef unsigned long long u64;

__device__ __forceinline__ u64 pack2(float a, float b) {
    u64 r;
    asm("mov.b64 %0, {%1, %2};" : "=l"(r) : "f"(a), "f"(b));
    return r;
}
__device__ __forceinline__ void fma2(u64 &d, u64 a, u64 b) {
    asm("fma.rn.f32x2 %0, %1, %2, %0;" : "+l"(d) : "l"(a), "l"(b));
}
__device__ __forceinline__ void unpack2(float &lo, float &hi, u64 v) {
    asm("mov.b64 {%0, %1}, %2;" : "=f"(lo), "=f"(hi) : "l"(v));
}

// Dynamic smem (34,816 B): sdict float[KK*EE] (32 KB, natural layout), snrm float[KK] (2 KB)
__global__ void __launch_bounds__(NT, 4) vq_kernel(const float* __restrict__ mu,
                                                   const float* __restrict__ dict,
                                                   float* __restrict__ out)
{
    extern __shared__ float smem_f[];
    float* sdict = smem_f;
    float* snrm  = smem_f + KK * EE;

    const int c = blockIdx.x;
    const int t = threadIdx.x;

    // ---- this thread's 2 batch rows (t, t+256), packed pairwise over e ----
    u64 muA[EE / 2], muB[EE / 2];
    {
        const float* m0 = mu + (size_t)t         * (CC * EE) + c * EE;
        const float* m1 = mu + (size_t)(t + 256) * (CC * EE) + c * EE;
#pragma unroll
        for (int e = 0; e < EE; e += 4) {
            float4 a = *(const float4*)(m0 + e);
            float4 b = *(const float4*)(m1 + e);
            muA[e / 2] = pack2(a.x, a.y);  muA[e / 2 + 1] = pack2(a.z, a.w);
            muB[e / 2] = pack2(b.x, b.y);  muB[e / 2 + 1] = pack2(b.z, b.w);
        }
    }

    // ---- dict[c] -> smem (natural layout) ----
    {
        const float4* g = (const float4*)(dict + (size_t)c * KK * EE);
        float4* sd4 = (float4*)sdict;
#pragma unroll 4
        for (int i = t; i < KK * EE / 4; i += NT) sd4[i] = g[i];
    }
    __syncthreads();

    // ---- -0.5 * ||d_k||^2 ----
#pragma unroll
    for (int k = t; k < KK; k += NT) {
        const float4* dv = (const float4*)(sdict + k * EE);
        float s = 0.f;
#pragma unroll
        for (int j = 0; j < 4; j++) {
            float4 v = dv[j];
            s = fmaf(v.x, v.x, s); s = fmaf(v.y, v.y, s);
            s = fmaf(v.z, v.z, s); s = fmaf(v.w, v.w, s);
        }
        snrm[k] = -0.5f * s;
    }
    __syncthreads();

    // ---- one_hot zero cursor: col4 = t&127 of rows 2*it + (t>>7) ----
    const float4 z4 = make_float4(0.f, 0.f, 0.f, 0.f);
    float4* ohp = (float4*)(out + OH_OFF)
                + (size_t)(t >> 7) * (CC * KK / 4)
                + (size_t)c * (KK / 4) + (t & 127);
    const size_t OH_STEP = 2 * ((size_t)CC * KK / 4);   // 2 batch rows per iter

    // ---- main argmax loop (k-pairs), zero stores interleaved ----
    float best0 = -3.4e38f, best1 = -3.4e38f;
    int i0 = 0, i1 = 0;
    const ulonglong2* dq = (const ulonglong2*)sdict;    // 8 per k-pair

#pragma unroll 2
    for (int it = 0; it < KK / 2; ++it) {
        const int k = 2 * it;
        __stcs(ohp, z4); ohp += OH_STEP;                // streaming zero store

        const float2 nn = *(const float2*)(snrm + k);   // one LDS.64
        float lo, hi, s;
        bool p;

        u64 a0, a1, a2, a3;
        {   // k
            ulonglong2 q0 = dq[0], q1 = dq[1], q2 = dq[2], q3 = dq[3];
            a0 = pack2(nn.x, 0.f); a1 = a0;
            fma2(a0, muA[0], q0.x); fma2(a1, muB[0], q0.x);
            fma2(a0, muA[1], q0.y); fma2(a1, muB[1], q0.y);
            fma2(a0, muA[2], q1.x); fma2(a1, muB[2], q1.x);
            fma2(a0, muA[3], q1.y); fma2(a1, muB[3], q1.y);
            fma2(a0, muA[4], q2.x); fma2(a1, muB[4], q2.x);
            fma2(a0, muA[5], q2.y); fma2(a1, muB[5], q2.y);
            fma2(a0, muA[6], q3.x); fma2(a1, muB[6], q3.x);
            fma2(a0, muA[7], q3.y); fma2(a1, muB[7], q3.y);
        }
        {   // k+1
            ulonglong2 q4 = dq[4], q5 = dq[5], q6 = dq[6], q7 = dq[7];
            a2 = pack2(nn.y, 0.f); a3 = a2;
            fma2(a2, muA[0], q4.x); fma2(a3, muB[0], q4.x);
            fma2(a2, muA[1], q4.y); fma2(a3, muB[1], q4.y);
            fma2(a2, muA[2], q5.x); fma2(a3, muB[2], q5.x);
            fma2(a2, muA[3], q5.y); fma2(a3, muB[3], q5.y);
            fma2(a2, muA[4], q6.x); fma2(a3, muB[4], q6.x);
            fma2(a2, muA[5], q6.y); fma2(a3, muB[5], q6.y);
            fma2(a2, muA[6], q7.x); fma2(a3, muB[6], q7.x);
            fma2(a2, muA[7], q7.y); fma2(a3, muB[7], q7.y);
        }

        // bookkeeping: FSETP (pred-as-data) + FMNMX (alu pipe) + SEL — no @P guards
        unpack2(lo, hi, a0); s = lo + hi;
        p = s > best0; best0 = fmaxf(best0, s); i0 = p ? k : i0;
        unpack2(lo, hi, a2); s = lo + hi;
        p = s > best0; best0 = fmaxf(best0, s); i0 = p ? (k + 1) : i0;
        unpack2(lo, hi, a1); s = lo + hi;
        p = s > best1; best1 = fmaxf(best1, s); i1 = p ? k : i1;
        unpack2(lo, hi, a3); s = lo + hi;
        p = s > best1; best1 = fmaxf(best1, s); i1 = p ? (k + 1) : i1;

        dq += 8;
    }

    __syncthreads();   // all zero-stores issued before the ones land

    // ---- write z / z_embed (streaming), scatter ones ----
    {
        const float* v = sdict + i0 * EE;
        size_t off = (size_t)t * (CC * EE) + c * EE;
#pragma unroll
        for (int e = 0; e < EE; e += 4) {
            float4 vv = *(const float4*)(v + e);
            float mx, my, mz, mw;
            unpack2(mx, my, muA[e / 2]);
            unpack2(mz, mw, muA[e / 2 + 1]);
            float4 zz;
            zz.x = mx + (vv.x - mx); zz.y = my + (vv.y - my);
            zz.z = mz + (vv.z - mz); zz.w = mw + (vv.w - mw);
            __stcs((float4*)(out + Z_OFF  + off + e), zz);
            __stcs((float4*)(out + ZE_OFF + off + e), vv);
        }
        out[OH_OFF + (size_t)t * (CC * KK) + (size_t)c * KK + i0] = 1.0f;
    }
    {
        const float* v = sdict + i1 * EE;
        size_t off = (size_t)(t + 256) * (CC * EE) + c * EE;
#pragma unroll
        for (int e = 0; e < EE; e += 4) {
            float4 vv = *(const float4*)(v + e);
            float mx, my, mz, mw;
            unpack2(mx, my, muB[e / 2]);
            unpack2(mz, mw, muB[e / 2 + 1]);
            float4 zz;
            zz.x = mx + (vv.x - mx); zz.y = my + (vv.y - my);
            zz.z = mz + (vv.z - mz); zz.w = mw + (vv.w - mw);
            __stcs((float4*)(out + Z_OFF  + off + e), zz);
            __stcs((float4*)(out + ZE_OFF + off + e), vv);
        }
        out[OH_OFF + (size_t)(t + 256) * (CC * KK) + (size_t)c * KK + i1] = 1.0f;
    }
}

extern "C" void kernel_launch(void* const* d_in, const int* in_sizes, int n_in,
                              void* d_out, int out_size)
{
    (void)in_sizes; (void)n_in; (void)out_size;
    const float* mu   = (const float*)d_in[0];
    const float* dict = (const float*)d_in[1];
    float* out = (float*)d_out;

    const int smem = (KK * EE + KK) * 4;   // 34,816 bytes
    cudaFuncSetAttribute(vq_kernel, cudaFuncAttributeMaxDynamicSharedMemorySize, smem);
    vq_kernel<<<CC, NT, smem>>>(mu, dict, out);
}

// round 7
// speedup vs baseline: 1.2746x; 1.0139x over previous
#include <cuda_runtime.h>

#define BB   512
#define CC   512
#define KK   512
#define EE   16
#define NT   128

#define Z_OFF   0
#define ZE_OFF  ((size_t)BB * CC * EE)            // 4,194,304 floats
#define OH_OFF  ((size_t)2 * BB * CC * EE)        // 8,388,608 floats

typedef unsigned long long u64;

__device__ float g_nrm[CC * KK];                  // -0.5*||dict[c][k]||^2

__device__ __forceinline__ u64 pack2(float a, float b) {
    u64 r;
    asm("mov.b64 %0, {%1, %2};" : "=l"(r) : "f"(a), "f"(b));
    return r;
}
__device__ __forceinline__ void fma2(u64 &d, u64 a, u64 b) {
    asm("fma.rn.f32x2 %0, %1, %2, %0;" : "+l"(d) : "l"(a), "l"(b));
}
__device__ __forceinline__ void unpack2(float &lo, float &hi, u64 v) {
    asm("mov.b64 {%0, %1}, %2;" : "=f"(lo), "=f"(hi) : "l"(v));
}

// Prefix kernel: norms for every (c, k). 512 blocks x 128 threads, 4 k each.
__global__ void __launch_bounds__(NT) norm_kernel(const float* __restrict__ dict)
{
    const int c = blockIdx.x;
    const int t = threadIdx.x;
#pragma unroll
    for (int j = 0; j < 4; ++j) {
        const int k = t + j * NT;
        const float4* dv = (const float4*)(dict + (size_t)c * KK * EE + k * EE);
        float s = 0.f;
#pragma unroll
        for (int q = 0; q < 4; ++q) {
            float4 v = dv[q];
            s = fmaf(v.x, v.x, s); s = fmaf(v.y, v.y, s);
            s = fmaf(v.z, v.z, s); s = fmaf(v.w, v.w, s);
        }
        g_nrm[c * KK + k] = -0.5f * s;
    }
}

// Main kernel: one (c, batch-half) per block. smem = dict[c] only (32 KB).
__global__ void __launch_bounds__(NT, 7) vq_kernel(const float* __restrict__ mu,
                                                   const float* __restrict__ dict,
                                                   float* __restrict__ out)
{
    extern __shared__ float sdict[];              // KK*EE floats, natural layout

    const int c = blockIdx.x >> 1;
    const int h = blockIdx.x & 1;
    const int t = threadIdx.x;
    const int r0 = h * 256 + t;                   // this thread's 2 batch rows
    const int r1 = r0 + 128;

    // ---- load 2 mu rows, packed pairwise over e ----
    u64 muA[EE / 2], muB[EE / 2];
    {
        const float* m0 = mu + (size_t)r0 * (CC * EE) + c * EE;
        const float* m1 = mu + (size_t)r1 * (CC * EE) + c * EE;
#pragma unroll
        for (int e = 0; e < EE; e += 4) {
            float4 a = *(const float4*)(m0 + e);
            float4 b = *(const float4*)(m1 + e);
            muA[e / 2] = pack2(a.x, a.y);  muA[e / 2 + 1] = pack2(a.z, a.w);
            muB[e / 2] = pack2(b.x, b.y);  muB[e / 2 + 1] = pack2(b.z, b.w);
        }
    }

    // ---- dict[c] -> smem ----
    {
        const float4* g = (const float4*)(dict + (size_t)c * KK * EE);
        float4* sd4 = (float4*)sdict;
#pragma unroll 4
        for (int i = t; i < KK * EE / 4; i += NT) sd4[i] = g[i];
    }
    __syncthreads();

    // ---- one_hot zero cursor: row h*256+it, col4 = t (128 x float4 = one 2KB row) ----
    const float4 z4 = make_float4(0.f, 0.f, 0.f, 0.f);
    float4* ohp = (float4*)(out + OH_OFF)
                + (size_t)(h * 256) * (CC * KK / 4)
                + (size_t)c * (KK / 4) + t;
    const size_t OH_STEP = (size_t)CC * KK / 4;   // one batch row per iter

    const float* nrmp = g_nrm + c * KK;

    // ---- main argmax loop (k-pairs) — loop body identical to R2 ----
    float best0 = -3.4e38f, best1 = -3.4e38f;
    int i0 = 0, i1 = 0;
    const ulonglong2* dq = (const ulonglong2*)sdict;    // 8 per k-pair

    for (int it = 0; it < KK / 2; ++it) {
        const int k = 2 * it;
        *ohp = z4; ohp += OH_STEP;                      // fire-and-forget zero

        const float2 nn = *(const float2*)(nrmp + k);   // uniform LDG.64, L1-hit
        float lo, hi, s;

        {   // k
            ulonglong2 q0 = dq[0], q1 = dq[1], q2 = dq[2], q3 = dq[3];
            u64 a0 = pack2(nn.x, 0.f), a1 = a0;
            fma2(a0, muA[0], q0.x); fma2(a1, muB[0], q0.x);
            fma2(a0, muA[1], q0.y); fma2(a1, muB[1], q0.y);
            fma2(a0, muA[2], q1.x); fma2(a1, muB[2], q1.x);
            fma2(a0, muA[3], q1.y); fma2(a1, muB[3], q1.y);
            fma2(a0, muA[4], q2.x); fma2(a1, muB[4], q2.x);
            fma2(a0, muA[5], q2.y); fma2(a1, muB[5], q2.y);
            fma2(a0, muA[6], q3.x); fma2(a1, muB[6], q3.x);
            fma2(a0, muA[7], q3.y); fma2(a1, muB[7], q3.y);
            unpack2(lo, hi, a0); s = lo + hi;
            if (s > best0) { best0 = s; i0 = k; }
            unpack2(lo, hi, a1); s = lo + hi;
            if (s > best1) { best1 = s; i1 = k; }
        }
        {   // k+1
            ulonglong2 q4 = dq[4], q5 = dq[5], q6 = dq[6], q7 = dq[7];
            u64 a2 = pack2(nn.y, 0.f), a3 = a2;
            fma2(a2, muA[0], q4.x); fma2(a3, muB[0], q4.x);
            fma2(a2, muA[1], q4.y); fma2(a3, muB[1], q4.y);
            fma2(a2, muA[2], q5.x); fma2(a3, muB[2], q5.x);
            fma2(a2, muA[3], q5.y); fma2(a3, muB[3], q5.y);
            fma2(a2, muA[4], q6.x); fma2(a3, muB[4], q6.x);
            fma2(a2, muA[5], q6.y); fma2(a3, muB[5], q6.y);
            fma2(a2, muA[6], q7.x); fma2(a3, muB[6], q7.x);
            fma2(a2, muA[7], q7.y); fma2(a3, muB[7], q7.y);
            unpack2(lo, hi, a2); s = lo + hi;
            if (s > best0) { best0 = s; i0 = k + 1; }
            unpack2(lo, hi, a3); s = lo + hi;
            if (s > best1) { best1 = s; i1 = k + 1; }
        }
        dq += 8;
    }

    __syncthreads();   // own block's zeros issued before its ones land

    // ---- write z / z_embed; scatter ones (rows owned by this block) ----
    {
        const float* v = sdict + i0 * EE;
        size_t off = (size_t)r0 * (CC * EE) + c * EE;
#pragma unroll
        for (int e = 0; e < EE; e += 4) {
            float4 vv = *(const float4*)(v + e);
            float mx, my, mz, mw;
            unpack2(mx, my, muA[e / 2]);
            unpack2(mz, mw, muA[e / 2 + 1]);
            float4 zz;
            zz.x = mx + (vv.x - mx); zz.y = my + (vv.y - my);
            zz.z = mz + (vv.z - mz); zz.w = mw + (vv.w - mw);
            *(float4*)(out + Z_OFF  + off + e) = zz;
            *(float4*)(out + ZE_OFF + off + e) = vv;
        }
        out[OH_OFF + (size_t)r0 * (CC * KK) + (size_t)c * KK + i0] = 1.0f;
    }
    {
        const float* v = sdict + i1 * EE;
        size_t off = (size_t)r1 * (CC * EE) + c * EE;
#pragma unroll
        for (int e = 0; e < EE; e += 4) {
            float4 vv = *(const float4*)(v + e);
            float mx, my, mz, mw;
            unpack2(mx, my, muB[e / 2]);
            unpack2(mz, mw, muB[e / 2 + 1]);
            float4 zz;
            zz.x = mx + (vv.x - mx); zz.y = my + (vv.y - my);
            zz.z = mz + (vv.z - mz); zz.w = mw + (vv.w - mw);
            *(float4*)(out + Z_OFF  + off + e) = zz;
            *(float4*)(out + ZE_OFF + off + e) = vv;
        }
        out[OH_OFF + (size_t)r1 * (CC * KK) + (size_t)c * KK + i1] = 1.0f;
    }
}

extern "C" void kernel_launch(void* const* d_in, const int* in_sizes, int n_in,
                              void* d_out, int out_size)
{
    (void)in_sizes; (void)n_in; (void)out_size;
    const float* mu   = (const float*)d_in[0];
    const float* dict = (const float*)d_in[1];
    float* out = (float*)d_out;

    norm_kernel<<<CC, NT>>>(dict);

    const int smem = KK * EE * 4;   // 32,768 bytes
    cudaFuncSetAttribute(vq_kernel, cudaFuncAttributeMaxDynamicSharedMemorySize, smem);
    vq_kernel<<<2 * CC, NT, smem>>>(mu, dict, out);
}